// round 8
// baseline (speedup 1.0000x reference)
#include <cuda_runtime.h>
#include <cuda_bf16.h>
#include <cfloat>

#define LEVELS 255.0f
#define EPS 1e-8f

// v8: 512-thread CTAs at occupancy 4 (vs 1024 @ occ 2).
// Same 2048 resident threads/SM, but 4 independent phase-staggered CTAs
// cover each other's barrier windows 3-deep, and each barrier spans only
// 16 warps. Each thread owns 8 float4 (full row per CTA); the upper 4 are
// staged through smem to stay under the 32-reg cap (proven time-neutral in R6).

__device__ __forceinline__ unsigned f2key(float f) {
    unsigned u = __float_as_uint(f);
    return (u & 0x80000000u) ? ~u : (u | 0x80000000u);
}
__device__ __forceinline__ float key2f(unsigned k) {
    unsigned u = (k & 0x80000000u) ? (k & 0x7FFFFFFFu) : ~k;
    return __uint_as_float(u);
}

__device__ __forceinline__ void minmax4(float4 v, float& mn, float& mx) {
    mn = fminf(mn, fminf(fminf(v.x, v.y), fminf(v.z, v.w)));
    mx = fmaxf(mx, fmaxf(fmaxf(v.x, v.y), fmaxf(v.z, v.w)));
}

__global__ __launch_bounds__(512, 4)
void perchannel_quant_kernel(const float* __restrict__ x,
                             float* __restrict__ out)
{
    const int row = blockIdx.x;
    const int tid = threadIdx.x;

    const float4* __restrict__ xrow =
        reinterpret_cast<const float4*>(x) + (size_t)row * 4096;
    float4* __restrict__ orow =
        reinterpret_cast<float4*>(out) + (size_t)row * 4096;

    __shared__ float4 sv[512 * 4];     // staged upper half of row (32 KB)
    __shared__ unsigned smn[16];
    __shared__ unsigned smx[16];

    float mn =  FLT_MAX;
    float mx = -FLT_MAX;

    // ---- lower half: 4 float4 in registers ----
    float4 v0 = __ldcs(&xrow[tid]);
    float4 v1 = __ldcs(&xrow[tid +  512]);
    float4 v2 = __ldcs(&xrow[tid + 1024]);
    float4 v3 = __ldcs(&xrow[tid + 1536]);

    // ---- upper half: 4 float4 staged to smem immediately ----
    #pragma unroll
    for (int k = 0; k < 4; k++) {
        float4 t = __ldcs(&xrow[tid + 2048 + k * 512]);
        sv[tid + k * 512] = t;
        minmax4(t, mn, mx);
    }

    minmax4(v0, mn, mx);
    minmax4(v1, mn, mx);
    minmax4(v2, mn, mx);
    minmax4(v3, mn, mx);

    // ---- warp reduce (REDUX.SYNC on monotonic keys) ----
    unsigned kmn = __reduce_min_sync(0xffffffffu, f2key(mn));
    unsigned kmx = __reduce_max_sync(0xffffffffu, f2key(mx));

    // ---- block reduce: 16 partials, ONE barrier, redundant REDUX ----
    const int lane = tid & 31;
    const int wid  = tid >> 5;
    if (lane == 0) { smn[wid] = kmn; smx[wid] = kmx; }
    __syncthreads();   // also orders sv[] stores before re-read

    // lanes 0..15 read the 16 partials, lanes 16..31 duplicate lane&15
    kmn = __reduce_min_sync(0xffffffffu, smn[lane & 15]);
    kmx = __reduce_max_sync(0xffffffffu, smx[lane & 15]);
    mn = key2f(kmn);
    mx = key2f(kmx);

    const float x_min = fminf(mn, 0.0f);
    const float x_max = fmaxf(mx, 0.0f);
    const float scale = fmaxf((x_max - x_min) * (1.0f / LEVELS), EPS);
    const float zero  = rintf(-x_min / scale);
    const float inv_scale = 1.0f / scale;
    const float qlo = -zero;
    const float qhi = LEVELS - zero;

    #define QUANT(e) do { \
        float q = rintf((e) * inv_scale); \
        q = fminf(fmaxf(q, qlo), qhi); \
        (e) = q * scale; \
    } while (0)

    // ---- reg-resident lower half ----
    QUANT(v0.x); QUANT(v0.y); QUANT(v0.z); QUANT(v0.w);
    __stcs(&orow[tid],        v0);
    QUANT(v1.x); QUANT(v1.y); QUANT(v1.z); QUANT(v1.w);
    __stcs(&orow[tid +  512], v1);
    QUANT(v2.x); QUANT(v2.y); QUANT(v2.z); QUANT(v2.w);
    __stcs(&orow[tid + 1024], v2);
    QUANT(v3.x); QUANT(v3.y); QUANT(v3.z); QUANT(v3.w);
    __stcs(&orow[tid + 1536], v3);

    // ---- smem-staged upper half ----
    #pragma unroll
    for (int k = 0; k < 4; k++) {
        float4 t = sv[tid + k * 512];
        QUANT(t.x); QUANT(t.y); QUANT(t.z); QUANT(t.w);
        __stcs(&orow[tid + 2048 + k * 512], t);
    }
    #undef QUANT
}

extern "C" void kernel_launch(void* const* d_in, const int* in_sizes, int n_in,
                              void* d_out, int out_size)
{
    const float* x = (const float*)d_in[0];
    float* out = (float*)d_out;
    perchannel_quant_kernel<<<4096, 512>>>(x, out);
}

// round 9
// speedup vs baseline: 1.0069x; 1.0069x over previous
#include <cuda_runtime.h>
#include <cuda_bf16.h>
#include <cfloat>

#define LEVELS 255.0f
#define EPS 1e-8f

// FINAL (= R7, measured best: kernel 76.7us @ 6.28 TB/s, wall 83.97us, rel_err 0).
// One CTA per row. Row = 16384 fp32 = 4096 float4; 1024 threads x 4 float4
// held in registers across the reduction. Single pass over HBM.
//  - .cs (evict-first) hints on load and store: input read once, output not re-read
//  - REDUX.SYNC warp min/max on monotonic float<->u32 keys (single-instruction
//    reduction, no 5-deep SHFL chain in the memory-idle window)
//  - ONE block barrier; every warp redundantly reduces the 32 partials
//  - centered-clamp epilogue: clip(rint(x/s)+z,0,255)-z == clip(rint(x/s),-z,255-z)
// Traffic floor is 512 MiB; measured 6.28 TB/s ~= the achievable mixed R/W
// stream ceiling for this read-reduce-write dependency structure.

__device__ __forceinline__ unsigned f2key(float f) {
    unsigned u = __float_as_uint(f);
    return (u & 0x80000000u) ? ~u : (u | 0x80000000u);
}
__device__ __forceinline__ float key2f(unsigned k) {
    unsigned u = (k & 0x80000000u) ? (k & 0x7FFFFFFFu) : ~k;
    return __uint_as_float(u);
}

__global__ __launch_bounds__(1024, 2)
void perchannel_quant_kernel(const float* __restrict__ x,
                             float* __restrict__ out)
{
    const int row = blockIdx.x;
    const int tid = threadIdx.x;

    const float4* __restrict__ xrow =
        reinterpret_cast<const float4*>(x) + (size_t)row * 4096;
    float4* __restrict__ orow =
        reinterpret_cast<float4*>(out) + (size_t)row * 4096;

    // ---- load 4 float4 per thread, coalesced, evict-first ----
    float4 v0 = __ldcs(&xrow[tid]);
    float4 v1 = __ldcs(&xrow[tid + 1024]);
    float4 v2 = __ldcs(&xrow[tid + 2048]);
    float4 v3 = __ldcs(&xrow[tid + 3072]);

    // ---- per-thread min/max ----
    float mn = fminf(fminf(fminf(v0.x, v0.y), fminf(v0.z, v0.w)),
                     fminf(fminf(v1.x, v1.y), fminf(v1.z, v1.w)));
    float mx = fmaxf(fmaxf(fmaxf(v0.x, v0.y), fmaxf(v0.z, v0.w)),
                     fmaxf(fmaxf(v1.x, v1.y), fmaxf(v1.z, v1.w)));
    mn = fminf(mn, fminf(fminf(fminf(v2.x, v2.y), fminf(v2.z, v2.w)),
                         fminf(fminf(v3.x, v3.y), fminf(v3.z, v3.w))));
    mx = fmaxf(mx, fmaxf(fmaxf(fmaxf(v2.x, v2.y), fmaxf(v2.z, v2.w)),
                         fmaxf(fmaxf(v3.x, v3.y), fmaxf(v3.z, v3.w))));

    // ---- warp reduce via single REDUX.SYNC on monotonic keys ----
    unsigned kmn = __reduce_min_sync(0xffffffffu, f2key(mn));
    unsigned kmx = __reduce_max_sync(0xffffffffu, f2key(mx));

    // ---- block reduce: partials to smem, ONE barrier, then every warp
    //      redundantly REDUX-reduces the 32 partial keys. ----
    __shared__ unsigned smn[32];
    __shared__ unsigned smx[32];

    const int lane = tid & 31;
    const int wid  = tid >> 5;
    if (lane == 0) { smn[wid] = kmn; smx[wid] = kmx; }
    __syncthreads();

    kmn = __reduce_min_sync(0xffffffffu, smn[lane]);
    kmx = __reduce_max_sync(0xffffffffu, smx[lane]);
    mn = key2f(kmn);
    mx = key2f(kmx);

    const float x_min = fminf(mn, 0.0f);
    const float x_max = fmaxf(mx, 0.0f);
    const float scale = fmaxf((x_max - x_min) * (1.0f / LEVELS), EPS);
    const float zero  = rintf(-x_min / scale);
    const float inv_scale = 1.0f / scale;
    const float qlo = -zero;           // clamp bounds in centered q-domain
    const float qhi = LEVELS - zero;

    // ---- quantize from registers, store evict-first ----
    #define QUANT(e) do { \
        float q = rintf((e) * inv_scale); \
        q = fminf(fmaxf(q, qlo), qhi); \
        (e) = q * scale; \
    } while (0)

    QUANT(v0.x); QUANT(v0.y); QUANT(v0.z); QUANT(v0.w);
    __stcs(&orow[tid],        v0);
    QUANT(v1.x); QUANT(v1.y); QUANT(v1.z); QUANT(v1.w);
    __stcs(&orow[tid + 1024], v1);
    QUANT(v2.x); QUANT(v2.y); QUANT(v2.z); QUANT(v2.w);
    __stcs(&orow[tid + 2048], v2);
    QUANT(v3.x); QUANT(v3.y); QUANT(v3.z); QUANT(v3.w);
    __stcs(&orow[tid + 3072], v3);
    #undef QUANT
}

extern "C" void kernel_launch(void* const* d_in, const int* in_sizes, int n_in,
                              void* d_out, int out_size)
{
    const float* x = (const float*)d_in[0];
    float* out = (float*)d_out;
    perchannel_quant_kernel<<<4096, 1024>>>(x, out);
}